// round 1
// baseline (speedup 1.0000x reference)
#include <cuda_runtime.h>
#include <cstdint>

// Shapes (fixed by the problem)
#define BATCH 8
#define CDIM 48
#define C3 144
#define HH 256
#define WWID 256
#define HWSZ 65536
#define HEADS 8
#define CPH 6          // CDIM / HEADS
#define NTOK 256       // 16*16 tokens
#define DDIM 1536      // CPH * 16 * 16

// Scratch (static device arrays; no runtime allocation)
#define QKV_SZ (8u*144u*65536u)            // 75,497,472 floats
#define TOK_PART 25165824u                 // 8*8*256*1536
#define OIMG_SZ 25165824u                  // 8*48*65536

__device__ float g_qkv[QKV_SZ];            // after 1x1 qkv conv, NCHW
__device__ float g_tok[3u*TOK_PART];       // q,k,v in token layout [(b*8+head)*256+n][1536]
__device__ float g_rnorm[2u*16384u];       // 1/max(||row||,eps) for q (part 0) and k (part 1)
__device__ float g_oimg[OIMG_SZ];          // attention output in image layout

// ---------------------------------------------------------------------------
// K1: qkv 1x1 conv.  out[b,o,p] = sum_c w[o,c] * x[b,c,p].  M=144,K=48 GEMM.
// Block: 64 pixels x all 144 outputs. 256 threads: thread = (og 0..15, pxg 0..15),
// 9 outputs x 4 pixels per thread.
// ---------------------------------------------------------------------------
__global__ __launch_bounds__(256) void k_qkv(const float* __restrict__ x,
                                             const float* __restrict__ wq) {
    __shared__ float ws[144 * 48];
    __shared__ float xs[48 * 64];
    int t = threadIdx.x;
    int b = blockIdx.y;
    int p0 = blockIdx.x * 64;

    for (int i = t; i < 144 * 48; i += 256) ws[i] = wq[i];
    const float* xb = x + (size_t)b * 48 * HWSZ + p0;
    for (int i = t; i < 48 * 64; i += 256) {
        int c = i >> 6, px = i & 63;
        xs[c * 64 + px] = xb[(size_t)c * HWSZ + px];
    }
    __syncthreads();

    int pxg = t & 15, og = t >> 4;
    float acc[9][4];
#pragma unroll
    for (int j = 0; j < 9; j++)
#pragma unroll
        for (int ii = 0; ii < 4; ii++) acc[j][ii] = 0.f;

#pragma unroll 4
    for (int k = 0; k < 48; k++) {
        float4 xv = *reinterpret_cast<const float4*>(&xs[k * 64 + pxg * 4]);
#pragma unroll
        for (int j = 0; j < 9; j++) {
            float w = ws[(og * 9 + j) * 48 + k];
            acc[j][0] += w * xv.x;
            acc[j][1] += w * xv.y;
            acc[j][2] += w * xv.z;
            acc[j][3] += w * xv.w;
        }
    }
    float* outb = g_qkv + (size_t)b * 144 * HWSZ + p0 + pxg * 4;
#pragma unroll
    for (int j = 0; j < 9; j++) {
        int o = og * 9 + j;
        float4 v = make_float4(acc[j][0], acc[j][1], acc[j][2], acc[j][3]);
        *reinterpret_cast<float4*>(&outb[(size_t)o * HWSZ]) = v;
    }
}

// ---------------------------------------------------------------------------
// K2: depthwise 3x3 (SAME, zero pad) + relayout into token format.
// Block = (b, ch, fy). Handles the 16 image rows {fy+16k}. Each row of 256 px
// maps to 16 token rows n=(fx,fy) with 16 contiguous d values each. Staged
// through smem so all gmem writes are 1KB contiguous.
// ---------------------------------------------------------------------------
__global__ __launch_bounds__(256) void k_dw(const float* __restrict__ wdw) {
    __shared__ float s[16 * 257];
    int t = threadIdx.x;
    int blk = blockIdx.x;
    int ch = blk >> 4, fy = blk & 15;
    int b = blockIdx.y;
    const float* src = g_qkv + ((size_t)(b * 144 + ch)) * HWSZ;

    float wd[9];
#pragma unroll
    for (int j = 0; j < 9; j++) wd[j] = wdw[ch * 9 + j];

    int x = t;
#pragma unroll 1
    for (int k = 0; k < 16; k++) {
        int y = k * 16 + fy;
        float v = 0.f;
#pragma unroll
        for (int dy = -1; dy <= 1; dy++) {
            int yy = y + dy;
            if ((unsigned)yy < 256u) {
                const float* row = src + yy * 256;
#pragma unroll
                for (int dx = -1; dx <= 1; dx++) {
                    int xx = x + dx;
                    if ((unsigned)xx < 256u) v += wd[(dy + 1) * 3 + dx + 1] * row[xx];
                }
            }
        }
        // token d within (c-block) = hh*16 + ww, hh=k, ww=x>>4; token fx = x&15
        s[(x & 15) * 257 + k * 16 + (x >> 4)] = v;
    }
    __syncthreads();

    int part = ch / 48, cc = ch % 48;
    int head = cc / 6, c = cc % 6;
    float* dst = g_tok + (size_t)part * TOK_PART +
                 ((size_t)((b * 8 + head) * 256)) * DDIM + c * 256;
#pragma unroll
    for (int fx = 0; fx < 16; fx++) {
        int n = fx * 16 + fy;
        dst[(size_t)n * DDIM + t] = s[fx * 257 + t];
    }
}

// ---------------------------------------------------------------------------
// K2b: reciprocal L2 norms of q and k token rows. 1 warp per row.
// rid = part*16384 + (b*8+head)*256 + n  (rows are contiguous across parts).
// ---------------------------------------------------------------------------
__global__ __launch_bounds__(256) void k_norm() {
    int t = threadIdx.x;
    int w = t >> 5, lane = t & 31;
    int rid = blockIdx.x * 8 + w;  // 0..32767
    const float* p = g_tok + (size_t)rid * DDIM;
    float ss = 0.f;
#pragma unroll
    for (int i = 0; i < 48; i++) {
        float v = p[lane + 32 * i];
        ss += v * v;
    }
#pragma unroll
    for (int off = 16; off; off >>= 1) ss += __shfl_xor_sync(0xffffffffu, ss, off);
    if (lane == 0) g_rnorm[rid] = 1.0f / fmaxf(sqrtf(ss), 1e-12f);
}

// ---------------------------------------------------------------------------
// K3: attention per (b,head). Grid (4 row-tiles, 64 bh). Block 256 threads.
// Row tile = 64 tokens: all fx (16) x fy in [fy0,fy0+4) -> row r = fx*4 + fyl.
// Phase 1: S(64x256) = Q K^T over d in 24 chunks of 64, acc in regs (8x8/thread).
// Then scale by rnorms*temperature, exp (no max needed: |q.k|<=1), row sums,
// softmax_1 denominator folded into epilogue.
// Phase 2: O(64x1536) = attn @ V in 24 chunks; each 64-d chunk = 16 full image
// rows, staged in smem and written coalesced to g_oimg (from_tokens fused).
// Dynamic smem: 149,056 B.
// ---------------------------------------------------------------------------
__global__ __launch_bounds__(256, 1) void k_attn(const float* __restrict__ temperature) {
    extern __shared__ float sm[];
    float* Qs   = sm;           // 4096   (phase 1)
    float* KsT  = sm + 4096;    // 16448  (phase 1, pitch 257)
    float* As   = sm;           // 16384  (phase 2, overlays Qs/KsT)
    float* Vs   = sm + 16384;   // 16384  (phase 2)
    float* Simg = sm + 32768;   // 4112   (16 x 257)
    float* rsum = sm + 36880;   // 64
    float* rqs  = sm + 36944;   // 64
    float* rks  = sm + 37008;   // 256

    int t = threadIdx.x;
    int fy0 = blockIdx.x * 4;
    int bh = blockIdx.y;
    int head = bh & 7;
    int b = bh >> 3;
    const float* gq = g_tok + (size_t)bh * NTOK * DDIM;
    const float* gk = g_tok + (size_t)TOK_PART + (size_t)bh * NTOK * DDIM;
    const float* gv = g_tok + 2u * (size_t)TOK_PART + (size_t)bh * NTOK * DDIM;

    int tr = t >> 5, tc = t & 31;
    float acc[8][8];
#pragma unroll
    for (int i = 0; i < 8; i++)
#pragma unroll
        for (int j = 0; j < 8; j++) acc[i][j] = 0.f;

    // -------- Phase 1: S = Q K^T --------
#pragma unroll 1
    for (int ck = 0; ck < 24; ck++) {
        int d0 = ck * 64;
#pragma unroll
        for (int i = 0; i < 16; i++) {
            int e = t + 256 * i;
            int r = e >> 6, cc2 = e & 63;
            int n = (r >> 2) * 16 + fy0 + (r & 3);
            Qs[r * 64 + cc2] = gq[(size_t)n * DDIM + d0 + cc2];
        }
#pragma unroll
        for (int i = 0; i < 64; i++) {
            int e = t + 256 * i;
            int m = e >> 6, kk = e & 63;
            KsT[kk * 257 + m] = gk[(size_t)m * DDIM + d0 + kk];
        }
        __syncthreads();
#pragma unroll 2
        for (int kk = 0; kk < 64; kk++) {
            float a[8], bb[8];
#pragma unroll
            for (int i = 0; i < 8; i++) a[i] = Qs[(tr * 8 + i) * 64 + kk];
#pragma unroll
            for (int j = 0; j < 8; j++) bb[j] = KsT[kk * 257 + tc + 32 * j];
#pragma unroll
            for (int i = 0; i < 8; i++)
#pragma unroll
                for (int j = 0; j < 8; j++) acc[i][j] += a[i] * bb[j];
        }
        __syncthreads();
    }

    // scale factors
    if (t < 64) {
        int n = (t >> 2) * 16 + fy0 + (t & 3);
        rqs[t] = g_rnorm[bh * 256 + n];
    }
    rks[t] = g_rnorm[16384 + bh * 256 + t];
    float tempv = temperature[head];
    __syncthreads();

    // exp (softmax_1 numerator) -> As
#pragma unroll
    for (int i = 0; i < 8; i++) {
        int r = tr * 8 + i;
        float rq = rqs[r];
#pragma unroll
        for (int j = 0; j < 8; j++) {
            int col = tc + 32 * j;
            acc[i][j] = __expf(acc[i][j] * rq * rks[col] * tempv);
        }
    }
#pragma unroll
    for (int i = 0; i < 8; i++)
#pragma unroll
        for (int j = 0; j < 8; j++)
            As[(tr * 8 + i) * 256 + tc + 32 * j] = acc[i][j];
    __syncthreads();

    // row sums: 4 lanes per row, quad shuffle reduce; fold +1 denominator
    {
        int r = t >> 2, seg = t & 3;
        float ssum = 0.f;
#pragma unroll
        for (int j = 0; j < 64; j++) ssum += As[r * 256 + seg * 64 + j];
        ssum += __shfl_xor_sync(0xffffffffu, ssum, 1);
        ssum += __shfl_xor_sync(0xffffffffu, ssum, 2);
        if (seg == 0) rsum[r] = 1.0f / (ssum + 1.0f);
    }
    __syncthreads();

    // -------- Phase 2: O = attn @ V, fused from_tokens --------
    float* oimg = g_oimg + ((size_t)(b * 48 + head * 6)) * HWSZ;
#pragma unroll 1
    for (int ck = 0; ck < 24; ck++) {
        int d0 = ck * 64;
#pragma unroll
        for (int i = 0; i < 64; i++) {
            int e = t + 256 * i;
            int m = e >> 6, cc2 = e & 63;
            Vs[m * 64 + cc2] = gv[(size_t)m * DDIM + d0 + cc2];
        }
        __syncthreads();

        float a2[8][2];
#pragma unroll
        for (int i = 0; i < 8; i++) { a2[i][0] = 0.f; a2[i][1] = 0.f; }
#pragma unroll 2
        for (int m = 0; m < 256; m++) {
            float b0 = Vs[m * 64 + tc];
            float b1 = Vs[m * 64 + tc + 32];
#pragma unroll
            for (int i = 0; i < 8; i++) {
                float a = As[(tr * 8 + i) * 256 + m];
                a2[i][0] += a * b0;
                a2[i][1] += a * b1;
            }
        }
        // stage 64-d chunk = 16 full image rows
#pragma unroll
        for (int i = 0; i < 8; i++) {
            int r = tr * 8 + i;
            int fx = r >> 2, fyl = r & 3;
            float sc = rsum[r];
#pragma unroll
            for (int j = 0; j < 2; j++) {
                int cidx = tc + 32 * j;
                int hl = cidx >> 4, ww = cidx & 15;
                Simg[(hl * 4 + fyl) * 257 + ww * 16 + fx] = a2[i][j] * sc;
            }
        }
        __syncthreads();
        int c = d0 >> 8;
        int hh0 = (d0 >> 4) & 15;
#pragma unroll
        for (int rr = 0; rr < 16; rr++) {
            int hl = rr >> 2, fyl = rr & 3;
            int y = (hh0 + hl) * 16 + fy0 + fyl;
            oimg[((size_t)c * 256 + y) * 256 + t] = Simg[rr * 257 + t];
        }
        __syncthreads();
    }
}

// ---------------------------------------------------------------------------
// K4: project_out 1x1 conv (48x48), same structure as K1. 3 outs x 4 px/thread.
// ---------------------------------------------------------------------------
__global__ __launch_bounds__(256) void k_proj(const float* __restrict__ wp,
                                              float* __restrict__ out) {
    __shared__ float ws[48 * 48];
    __shared__ float xs[48 * 64];
    int t = threadIdx.x;
    int b = blockIdx.y;
    int p0 = blockIdx.x * 64;

    for (int i = t; i < 48 * 48; i += 256) ws[i] = wp[i];
    const float* xb = g_oimg + (size_t)b * 48 * HWSZ + p0;
    for (int i = t; i < 48 * 64; i += 256) {
        int c = i >> 6, px = i & 63;
        xs[c * 64 + px] = xb[(size_t)c * HWSZ + px];
    }
    __syncthreads();

    int pxg = t & 15, og = t >> 4;  // o = og*3 + j
    float acc[3][4];
#pragma unroll
    for (int j = 0; j < 3; j++)
#pragma unroll
        for (int ii = 0; ii < 4; ii++) acc[j][ii] = 0.f;

#pragma unroll 4
    for (int k = 0; k < 48; k++) {
        float4 xv = *reinterpret_cast<const float4*>(&xs[k * 64 + pxg * 4]);
#pragma unroll
        for (int j = 0; j < 3; j++) {
            float w = ws[(og * 3 + j) * 48 + k];
            acc[j][0] += w * xv.x;
            acc[j][1] += w * xv.y;
            acc[j][2] += w * xv.z;
            acc[j][3] += w * xv.w;
        }
    }
    float* ob = out + (size_t)b * 48 * HWSZ + p0 + pxg * 4;
#pragma unroll
    for (int j = 0; j < 3; j++) {
        int o = og * 3 + j;
        float4 v = make_float4(acc[j][0], acc[j][1], acc[j][2], acc[j][3]);
        *reinterpret_cast<float4*>(&ob[(size_t)o * HWSZ]) = v;
    }
}

extern "C" void kernel_launch(void* const* d_in, const int* in_sizes, int n_in,
                              void* d_out, int out_size) {
    const float* x      = (const float*)d_in[0];  // (8,48,256,256)
    const float* w_qkv  = (const float*)d_in[1];  // (144,48)
    const float* w_dw   = (const float*)d_in[2];  // (144,1,3,3)
    const float* w_proj = (const float*)d_in[3];  // (48,48)
    const float* temp   = (const float*)d_in[4];  // (8,1,1)
    float* out = (float*)d_out;

    cudaFuncSetAttribute(k_attn, cudaFuncAttributeMaxDynamicSharedMemorySize,
                         160 * 1024);

    k_qkv<<<dim3(1024, 8), 256>>>(x, w_qkv);
    k_dw<<<dim3(2304, 8), 256>>>(w_dw);
    k_norm<<<4096, 256>>>();
    k_attn<<<dim3(4, 64), 256, 37264 * sizeof(float)>>>(temp);
    k_proj<<<dim3(1024, 8), 256>>>(w_proj, out);
}

// round 4
// speedup vs baseline: 1.2439x; 1.2439x over previous
#include <cuda_runtime.h>
#include <cuda_bf16.h>
#include <cstdint>

#define HWSZ 65536
#define DDIM 1536
#define TOKB_PART (64u*256u*1536u)

__device__ float g_qkv[8u*144u*65536u];
__device__ __nv_bfloat16 g_tokb[3u*TOKB_PART];   // q,k,v(hi) bf16 [part][bh][tok][d]
__device__ __nv_bfloat16 g_vlo[TOKB_PART];       // v residual (v - bf16(v))
__device__ float g_rnorm[2u*16384u];
__device__ float g_oimg[8u*48u*65536u];

__device__ __forceinline__ uint32_t smem_u32(const void* p) {
    uint32_t a;
    asm("{ .reg .u64 t; cvta.to.shared.u64 t, %1; cvt.u32.u64 %0, t; }" : "=r"(a) : "l"(p));
    return a;
}
#define SW128(o) ((o) ^ (((o) >> 3) & 0x70))

__device__ __forceinline__ void ldsm_x4(uint32_t* r, uint32_t a) {
    asm volatile("ldmatrix.sync.aligned.m8n8.x4.shared.b16 {%0,%1,%2,%3}, [%4];"
                 : "=r"(r[0]), "=r"(r[1]), "=r"(r[2]), "=r"(r[3]) : "r"(a));
}
__device__ __forceinline__ void ldsm_x2(uint32_t* r, uint32_t a) {
    asm volatile("ldmatrix.sync.aligned.m8n8.x2.shared.b16 {%0,%1}, [%2];"
                 : "=r"(r[0]), "=r"(r[1]) : "r"(a));
}
__device__ __forceinline__ void ldsm_x2t(uint32_t* r, uint32_t a) {
    asm volatile("ldmatrix.sync.aligned.m8n8.x2.trans.shared.b16 {%0,%1}, [%2];"
                 : "=r"(r[0]), "=r"(r[1]) : "r"(a));
}
__device__ __forceinline__ void mma_bf16(float* c, const uint32_t* a, const uint32_t* b) {
    asm volatile(
        "mma.sync.aligned.m16n8k16.row.col.f32.bf16.bf16.f32 "
        "{%0,%1,%2,%3}, {%4,%5,%6,%7}, {%8,%9}, {%0,%1,%2,%3};"
        : "+f"(c[0]), "+f"(c[1]), "+f"(c[2]), "+f"(c[3])
        : "r"(a[0]), "r"(a[1]), "r"(a[2]), "r"(a[3]), "r"(b[0]), "r"(b[1]));
}

// ---------------------------------------------------------------------------
// K1: qkv 1x1 conv
// ---------------------------------------------------------------------------
__global__ __launch_bounds__(256) void k_qkv(const float* __restrict__ x,
                                             const float* __restrict__ wq) {
    __shared__ float ws[144 * 48];
    __shared__ float xs[48 * 64];
    int t = threadIdx.x;
    int b = blockIdx.y;
    int p0 = blockIdx.x * 64;

    for (int i = t; i < 144 * 48; i += 256) ws[i] = wq[i];
    const float* xb = x + (size_t)b * 48 * HWSZ + p0;
    for (int i = t; i < 48 * 64; i += 256) {
        int c = i >> 6, px = i & 63;
        xs[c * 64 + px] = xb[(size_t)c * HWSZ + px];
    }
    __syncthreads();

    int pxg = t & 15, og = t >> 4;
    float acc[9][4];
#pragma unroll
    for (int j = 0; j < 9; j++)
#pragma unroll
        for (int ii = 0; ii < 4; ii++) acc[j][ii] = 0.f;

#pragma unroll 4
    for (int k = 0; k < 48; k++) {
        float4 xv = *reinterpret_cast<const float4*>(&xs[k * 64 + pxg * 4]);
#pragma unroll
        for (int j = 0; j < 9; j++) {
            float w = ws[(og * 9 + j) * 48 + k];
            acc[j][0] += w * xv.x; acc[j][1] += w * xv.y;
            acc[j][2] += w * xv.z; acc[j][3] += w * xv.w;
        }
    }
    float* outb = g_qkv + (size_t)b * 144 * HWSZ + p0 + pxg * 4;
#pragma unroll
    for (int j = 0; j < 9; j++) {
        int o = og * 9 + j;
        float4 v = make_float4(acc[j][0], acc[j][1], acc[j][2], acc[j][3]);
        *reinterpret_cast<float4*>(&outb[(size_t)o * HWSZ]) = v;
    }
}

// ---------------------------------------------------------------------------
// K2: depthwise 3x3 + relayout to bf16 tokens; V also emits lo residual
// ---------------------------------------------------------------------------
__global__ __launch_bounds__(256) void k_dw(const float* __restrict__ wdw) {
    __shared__ float s[16 * 257];
    int t = threadIdx.x;
    int blk = blockIdx.x;
    int ch = blk >> 4, fy = blk & 15;
    int b = blockIdx.y;
    const float* src = g_qkv + ((size_t)(b * 144 + ch)) * HWSZ;

    float wd[9];
#pragma unroll
    for (int j = 0; j < 9; j++) wd[j] = wdw[ch * 9 + j];

    int x = t;
#pragma unroll 1
    for (int k = 0; k < 16; k++) {
        int y = k * 16 + fy;
        float v = 0.f;
#pragma unroll
        for (int dy = -1; dy <= 1; dy++) {
            int yy = y + dy;
            if ((unsigned)yy < 256u) {
                const float* row = src + yy * 256;
#pragma unroll
                for (int dx = -1; dx <= 1; dx++) {
                    int xx = x + dx;
                    if ((unsigned)xx < 256u) v += wd[(dy + 1) * 3 + dx + 1] * row[xx];
                }
            }
        }
        s[(x & 15) * 257 + k * 16 + (x >> 4)] = v;
    }
    __syncthreads();

    int part = ch / 48, cc = ch % 48;
    int head = cc / 6, c = cc % 6;
    size_t base = (size_t)part * TOKB_PART +
                  ((size_t)((b * 8 + head) * 256)) * DDIM + c * 256;
#pragma unroll
    for (int fx = 0; fx < 16; fx++) {
        int n = fx * 16 + fy;
        float v = s[fx * 257 + t];
        __nv_bfloat16 h = __float2bfloat16(v);
        g_tokb[base + (size_t)n * DDIM + t] = h;
        if (part == 2) {
            size_t vbase = ((size_t)((b * 8 + head) * 256)) * DDIM + c * 256;
            g_vlo[vbase + (size_t)n * DDIM + t] = __float2bfloat16(v - __bfloat162float(h));
        }
    }
}

// ---------------------------------------------------------------------------
// K2b: reciprocal L2 norms of bf16 token rows
// ---------------------------------------------------------------------------
__global__ __launch_bounds__(256) void k_norm() {
    int t = threadIdx.x;
    int w = t >> 5, lane = t & 31;
    int rid = blockIdx.x * 8 + w;
    const __nv_bfloat16* p = g_tokb + (size_t)rid * DDIM;
    float ss = 0.f;
#pragma unroll
    for (int i = 0; i < 48; i++) {
        float v = __bfloat162float(p[lane + 32 * i]);
        ss += v * v;
    }
#pragma unroll
    for (int off = 16; off; off >>= 1) ss += __shfl_xor_sync(0xffffffffu, ss, off);
    if (lane == 0) g_rnorm[rid] = 1.0f / fmaxf(sqrtf(ss), 1e-12f);
}

// ---------------------------------------------------------------------------
// K3: attention via mma.sync, hi/lo precision on GEMM2.
// smem: Ahi[0,67584) Alo[67584,135168) Tc[135168,+65536) scal[200704,204800)
// Phase2 O = Ahi*Vhi + Ahi*Vlo + Alo*Vhi.
// ---------------------------------------------------------------------------
__global__ __launch_bounds__(256, 1) void k_attn(const float* __restrict__ temperature) {
    extern __shared__ __align__(128) char sm[];
    char* Ahi = sm;
    char* Alo = sm + 67584;
    char* Tc  = sm + 135168;
    float* rqs  = (float*)(sm + 200704);  // 128
    float* rks  = rqs + 128;              // 256
    float* rsp  = rks + 256;              // 512
    float* rsum = rsp + 512;              // 128

    const int t = threadIdx.x;
    const int warp = t >> 5, lane = t & 31;
    const int mt = blockIdx.x;
    const int bh = blockIdx.y;
    const int head = bh & 7;
    const int b = bh >> 3;

    const __nv_bfloat16* gq = g_tokb + (size_t)bh * 256 * DDIM;
    const __nv_bfloat16* gk = g_tokb + (size_t)TOKB_PART + (size_t)bh * 256 * DDIM;
    const __nv_bfloat16* gv = g_tokb + 2u * (size_t)TOKB_PART + (size_t)bh * 256 * DDIM;
    const __nv_bfloat16* gvl = g_vlo + (size_t)bh * 256 * DDIM;

    const uint32_t aAh = smem_u32(Ahi);
    const uint32_t aAl = smem_u32(Alo);
    const uint32_t aV  = smem_u32(Tc);       // phase1: Q here, K at +16384
    const uint32_t aK  = aV + 16384;
    const uint32_t aVl = aV + 32768;

    if (t < 128) {
        int n = (t >> 3) * 16 + mt * 8 + (t & 7);
        rqs[t] = g_rnorm[bh * 256 + n] * temperature[head];
    }
    rks[t] = g_rnorm[16384 + bh * 256 + t];

    const int warpM = warp >> 2, warpN = warp & 3;
    float acc[4][8][4];
#pragma unroll
    for (int i = 0; i < 4; i++)
#pragma unroll
        for (int j = 0; j < 8; j++)
#pragma unroll
            for (int q = 0; q < 4; q++) acc[i][j][q] = 0.f;

    // ---------------- Phase 1: S = Q K^T (bf16) ----------------
#pragma unroll 1
    for (int ck = 0; ck < 24; ck++) {
        int d0 = ck * 64;
#pragma unroll
        for (int i = 0; i < 4; i++) {
            int s = t + 256 * i; int r = s >> 3, cs = s & 7;
            int n = (r >> 3) * 16 + mt * 8 + (r & 7);
            uint4 v = *(const uint4*)(gq + (size_t)n * DDIM + d0 + cs * 8);
            *(uint4*)(Tc + SW128(r * 128 + cs * 16)) = v;
        }
#pragma unroll
        for (int i = 0; i < 8; i++) {
            int s = t + 256 * i; int m2 = s >> 3, cs = s & 7;
            uint4 v = *(const uint4*)(gk + (size_t)m2 * DDIM + d0 + cs * 8);
            *(uint4*)(Tc + 16384 + SW128(m2 * 128 + cs * 16)) = v;
        }
        __syncthreads();

        int lm = lane & 15;
#pragma unroll
        for (int kk = 0; kk < 4; kk++) {
            int k0 = kk * 16;
            uint32_t af[4][4];
#pragma unroll
            for (int i = 0; i < 4; i++) {
                int row = warpM * 64 + i * 16 + lm;
                ldsm_x4(af[i], aV + SW128(row * 128 + k0 * 2 + ((lane >> 4) << 4)));
            }
            uint32_t bfg[8][2];
#pragma unroll
            for (int j = 0; j < 8; j++) {
                int row = warpN * 64 + j * 8 + (lm & 7);
                ldsm_x2(bfg[j], aK + SW128(row * 128 + (k0 + ((lm >> 3) << 3)) * 2));
            }
#pragma unroll
            for (int i = 0; i < 4; i++)
#pragma unroll
                for (int j = 0; j < 8; j++) mma_bf16(acc[i][j], af[i], bfg[j]);
        }
        __syncthreads();
    }

    // -------- Epilogue 1: exp, rowsum, A -> smem as hi+lo bf16 --------
#pragma unroll
    for (int i = 0; i < 4; i++) {
        int m0 = warpM * 64 + i * 16 + (lane >> 2);
        int m1 = m0 + 8;
        float q0 = rqs[m0], q1 = rqs[m1];
        float r0 = 0.f, r1 = 0.f;
#pragma unroll
        for (int j = 0; j < 8; j++) {
            int n0 = warpN * 64 + j * 8 + ((lane & 3) << 1);
            float k0v = rks[n0], k1v = rks[n0 + 1];
            float e00 = __expf(acc[i][j][0] * q0 * k0v);
            float e01 = __expf(acc[i][j][1] * q0 * k1v);
            float e10 = __expf(acc[i][j][2] * q1 * k0v);
            float e11 = __expf(acc[i][j][3] * q1 * k1v);
            r0 += e00 + e01; r1 += e10 + e11;
            uint32_t p0, p1;
            asm("cvt.rn.bf16x2.f32 %0, %1, %2;" : "=r"(p0) : "f"(e01), "f"(e00));
            asm("cvt.rn.bf16x2.f32 %0, %1, %2;" : "=r"(p1) : "f"(e11), "f"(e10));
            // lo residuals (bf16->fp32 is <<16)
            float h00 = __uint_as_float(p0 << 16),  h01 = __uint_as_float(p0 & 0xFFFF0000u);
            float h10 = __uint_as_float(p1 << 16),  h11 = __uint_as_float(p1 & 0xFFFF0000u);
            uint32_t q0p, q1p;
            asm("cvt.rn.bf16x2.f32 %0, %1, %2;" : "=r"(q0p) : "f"(e01 - h01), "f"(e00 - h00));
            asm("cvt.rn.bf16x2.f32 %0, %1, %2;" : "=r"(q1p) : "f"(e11 - h11), "f"(e10 - h10));
            *(uint32_t*)(Ahi + m0 * 528 + n0 * 2) = p0;
            *(uint32_t*)(Ahi + m1 * 528 + n0 * 2) = p1;
            *(uint32_t*)(Alo + m0 * 528 + n0 * 2) = q0p;
            *(uint32_t*)(Alo + m1 * 528 + n0 * 2) = q1p;
        }
        r0 += __shfl_xor_sync(0xffffffffu, r0, 1);
        r0 += __shfl_xor_sync(0xffffffffu, r0, 2);
        r1 += __shfl_xor_sync(0xffffffffu, r1, 1);
        r1 += __shfl_xor_sync(0xffffffffu, r1, 2);
        if ((lane & 3) == 0) {
            rsp[warpN * 128 + m0] = r0;
            rsp[warpN * 128 + m1] = r1;
        }
    }
    __syncthreads();
    if (t < 128) rsum[t] = 1.0f / (rsp[t] + rsp[128 + t] + rsp[256 + t] + rsp[384 + t] + 1.0f);
    __syncthreads();

    // -------- Phase 2: O = Ahi*Vhi + Ahi*Vlo + Alo*Vhi, fused from_tokens --------
    float* oimg_base = g_oimg + ((size_t)(b * 48 + head * 6)) * HWSZ;
    const int fy0 = mt * 8;
    const int lm = lane & 15;
#pragma unroll 1
    for (int ck = 0; ck < 24; ck++) {
        int d0 = ck * 64;
#pragma unroll
        for (int i = 0; i < 8; i++) {
            int s = t + 256 * i; int m2 = s >> 3, cs = s & 7;
            uint4 v = *(const uint4*)(gv + (size_t)m2 * DDIM + d0 + cs * 8);
            *(uint4*)(Tc + SW128(m2 * 128 + cs * 16)) = v;
            uint4 vl = *(const uint4*)(gvl + (size_t)m2 * DDIM + d0 + cs * 8);
            *(uint4*)(Tc + 32768 + SW128(m2 * 128 + cs * 16)) = vl;
        }
        __syncthreads();

        float oacc[8][4];
#pragma unroll
        for (int j = 0; j < 8; j++)
#pragma unroll
            for (int q = 0; q < 4; q++) oacc[j][q] = 0.f;

        int m0r = warp * 16;
#pragma unroll 1
        for (int kk = 0; kk < 16; kk++) {
            int n0 = kk * 16;
            uint32_t afh[4], afl[4];
            ldsm_x4(afh, aAh + (m0r + lm) * 528 + (n0 + ((lane >> 4) << 3)) * 2);
            ldsm_x4(afl, aAl + (m0r + lm) * 528 + (n0 + ((lane >> 4) << 3)) * 2);
#pragma unroll
            for (int j = 0; j < 8; j++) {
                uint32_t bh2[2], bl2[2];
                ldsm_x2t(bh2, aV + SW128((n0 + lm) * 128 + j * 16));
                ldsm_x2t(bl2, aVl + SW128((n0 + lm) * 128 + j * 16));
                mma_bf16(oacc[j], afh, bh2);
                mma_bf16(oacc[j], afh, bl2);
                mma_bf16(oacc[j], afl, bh2);
            }
        }
        __syncthreads();  // V dead; stage overlays

        float* stg = (float*)Tc;
        int r0 = m0r + (lane >> 2), r1 = r0 + 8;
        float s0 = rsum[r0], s1 = rsum[r1];
        int fx0 = r0 >> 3, fyl0 = r0 & 7;
        int fx1 = r1 >> 3, fyl1 = r1 & 7;
#pragma unroll
        for (int j = 0; j < 8; j++) {
            int cd = j * 8 + ((lane & 3) << 1);
            int hl = cd >> 4, ww = cd & 15;
            stg[(hl * 8 + fyl0) * 260 + ww * 16 + fx0]       = oacc[j][0] * s0;
            stg[(hl * 8 + fyl0) * 260 + (ww + 1) * 16 + fx0] = oacc[j][1] * s0;
            stg[(hl * 8 + fyl1) * 260 + ww * 16 + fx1]       = oacc[j][2] * s1;
            stg[(hl * 8 + fyl1) * 260 + (ww + 1) * 16 + fx1] = oacc[j][3] * s1;
        }
        __syncthreads();
        int c = ck >> 2, hh0 = (ck & 3) * 4;
#pragma unroll
        for (int rr = 0; rr < 32; rr++) {
            int y = (hh0 + (rr >> 3)) * 16 + fy0 + (rr & 7);
            oimg_base[((size_t)c * 256 + y) * 256 + t] = stg[rr * 260 + t];
        }
        __syncthreads();
    }
}

// ---------------------------------------------------------------------------
// K4: project_out 1x1 conv
// ---------------------------------------------------------------------------
__global__ __launch_bounds__(256) void k_proj(const float* __restrict__ wp,
                                              float* __restrict__ out) {
    __shared__ float ws[48 * 48];
    __shared__ float xs[48 * 64];
    int t = threadIdx.x;
    int b = blockIdx.y;
    int p0 = blockIdx.x * 64;

    for (int i = t; i < 48 * 48; i += 256) ws[i] = wp[i];
    const float* xb = g_oimg + (size_t)b * 48 * HWSZ + p0;
    for (int i = t; i < 48 * 64; i += 256) {
        int c = i >> 6, px = i & 63;
        xs[c * 64 + px] = xb[(size_t)c * HWSZ + px];
    }
    __syncthreads();

    int pxg = t & 15, og = t >> 4;
    float acc[3][4];
#pragma unroll
    for (int j = 0; j < 3; j++)
#pragma unroll
        for (int ii = 0; ii < 4; ii++) acc[j][ii] = 0.f;

#pragma unroll 4
    for (int k = 0; k < 48; k++) {
        float4 xv = *reinterpret_cast<const float4*>(&xs[k * 64 + pxg * 4]);
#pragma unroll
        for (int j = 0; j < 3; j++) {
            float w = ws[(og * 3 + j) * 48 + k];
            acc[j][0] += w * xv.x; acc[j][1] += w * xv.y;
            acc[j][2] += w * xv.z; acc[j][3] += w * xv.w;
        }
    }
    float* ob = out + (size_t)b * 48 * HWSZ + p0 + pxg * 4;
#pragma unroll
    for (int j = 0; j < 3; j++) {
        int o = og * 3 + j;
        float4 v = make_float4(acc[j][0], acc[j][1], acc[j][2], acc[j][3]);
        *reinterpret_cast<float4*>(&ob[(size_t)o * HWSZ]) = v;
    }
}

extern "C" void kernel_launch(void* const* d_in, const int* in_sizes, int n_in,
                              void* d_out, int out_size) {
    const float* x      = (const float*)d_in[0];
    const float* w_qkv  = (const float*)d_in[1];
    const float* w_dw   = (const float*)d_in[2];
    const float* w_proj = (const float*)d_in[3];
    const float* temp   = (const float*)d_in[4];
    float* out = (float*)d_out;

    cudaFuncSetAttribute(k_attn, cudaFuncAttributeMaxDynamicSharedMemorySize, 208 * 1024);

    k_qkv<<<dim3(1024, 8), 256>>>(x, w_qkv);
    k_dw<<<dim3(2304, 8), 256>>>(w_dw);
    k_norm<<<4096, 256>>>();
    k_attn<<<dim3(2, 64), 256, 204800>>>(temp);
    k_proj<<<dim3(1024, 8), 256>>>(w_proj, out);
}